// round 2
// baseline (speedup 1.0000x reference)
#include <cuda_runtime.h>
#include <cuda_bf16.h>

// Problem constants (fixed by the reference)
#define M_ITEMS 20001      // emb rows / segments
#define EDIM    128
#define NE      640000     // edges (divisible by 256)

// Scratch (device globals: no runtime allocation allowed)
__device__ float g_item[M_ITEMS * EDIM];   // item_scaled = emb @ W + b
__device__ float g_a1[M_ITEMS];            // item_scaled . W_att[:128]
__device__ float g_a2[M_ITEMS];            // item_scaled . W_att[128:]
__device__ float g_score[NE];              // raw exp scores per edge
__device__ int   g_segstart[M_ITEMS + 1];  // segment boundaries (edges sorted by src)
__device__ int2  g_edge[NE];               // canonical (src, dst) pairs
__device__ int   g_is64;                   // 1 if edge input is int64-layout

// ---------------------------------------------------------------------------
// K0a: sniff edge dtype. If int64, every odd 32-bit word is a zero high-half
// (values in [0, 20000]); if int32, odd words are random dst indices.
// Reads only the first 8192 words (safe under both layouts). Deterministic.
// ---------------------------------------------------------------------------
__global__ void k_detect(const unsigned int* __restrict__ w) {
    __shared__ unsigned int red[8];
    unsigned int v = 0;
    for (int k = threadIdx.x; k < 4096; k += 256) v |= w[2 * k + 1];
#pragma unroll
    for (int o = 16; o; o >>= 1) v |= __shfl_xor_sync(0xFFFFFFFFu, v, o);
    if ((threadIdx.x & 31) == 0) red[threadIdx.x >> 5] = v;
    __syncthreads();
    if (threadIdx.x == 0) {
        unsigned int t = 0;
#pragma unroll
        for (int j = 0; j < 8; ++j) t |= red[j];
        g_is64 = (t == 0) ? 1 : 0;
    }
}

// ---------------------------------------------------------------------------
// K0b: normalize edges to canonical int2 (src, dst).
// ---------------------------------------------------------------------------
__global__ void __launch_bounds__(256) k_norm(const int* __restrict__ ew) {
    const int e = blockIdx.x * blockDim.x + threadIdx.x;   // NE % 256 == 0
    int2 p;
    if (g_is64) { p.x = ew[4 * e]; p.y = ew[4 * e + 2]; }
    else        { p.x = ew[2 * e]; p.y = ew[2 * e + 1]; }
    g_edge[e] = p;
}

// ---------------------------------------------------------------------------
// K1: item_scaled = emb_mat @ W_scale + b_scale   (20001 x 128 x 128, fp32)
// 64-row tile per block, 256 threads, 8x4 register micro-tile, K split in 2.
// ---------------------------------------------------------------------------
__global__ void __launch_bounds__(256) k_gemm(const float* __restrict__ A,
                                              const float* __restrict__ W,
                                              const float* __restrict__ bias) {
    __shared__ alignas(16) float sW[64 * 128];
    __shared__ alignas(16) float sA[64 * 64];   // transposed: sA[k][row]

    const int t  = threadIdx.x;
    const int tx = t & 31;          // column group: cols [4*tx, 4*tx+3]
    const int ty = t >> 5;          // row group: rows [8*ty, 8*ty+7]
    const int r0 = blockIdx.x * 64;

    float acc[8][4];
#pragma unroll
    for (int j = 0; j < 8; ++j)
#pragma unroll
        for (int c = 0; c < 4; ++c) acc[j][c] = 0.f;

    for (int kh = 0; kh < 2; ++kh) {
        const int k0 = kh * 64;
        // ---- load W[k0:k0+64][0:128] (8192 floats) coalesced ----
        {
            const float4* Wg  = reinterpret_cast<const float4*>(W + (size_t)k0 * 128);
            float4*       sW4 = reinterpret_cast<float4*>(sW);
#pragma unroll
            for (int i = 0; i < 8; ++i) sW4[t + i * 256] = Wg[t + i * 256];
        }
        // ---- load A rows [r0, r0+64), k in [k0, k0+64), transposed ----
        {
            const int row  = t >> 2;               // 0..63
            const int kq   = (t & 3) * 16;         // 0,16,32,48
            const int grow = min(r0 + row, M_ITEMS - 1);
            const float4* Ag = reinterpret_cast<const float4*>(A + (size_t)grow * 128 + k0 + kq);
#pragma unroll
            for (int q = 0; q < 4; ++q) {
                float4 v = Ag[q];
                const int kk = kq + q * 4;
                sA[(kk + 0) * 64 + row] = v.x;
                sA[(kk + 1) * 64 + row] = v.y;
                sA[(kk + 2) * 64 + row] = v.z;
                sA[(kk + 3) * 64 + row] = v.w;
            }
        }
        __syncthreads();

        const float4* sW4 = reinterpret_cast<const float4*>(sW);
        const float4* sA4 = reinterpret_cast<const float4*>(sA);
#pragma unroll 8
        for (int k = 0; k < 64; ++k) {
            const float4 w4  = sW4[k * 32 + tx];
            const float4 a0  = sA4[k * 16 + ty * 2];
            const float4 a1v = sA4[k * 16 + ty * 2 + 1];
            const float a[8] = {a0.x, a0.y, a0.z, a0.w, a1v.x, a1v.y, a1v.z, a1v.w};
#pragma unroll
            for (int j = 0; j < 8; ++j) {
                acc[j][0] += a[j] * w4.x;
                acc[j][1] += a[j] * w4.y;
                acc[j][2] += a[j] * w4.z;
                acc[j][3] += a[j] * w4.w;
            }
        }
        __syncthreads();
    }

    const float4 b4 = reinterpret_cast<const float4*>(bias)[tx];
#pragma unroll
    for (int j = 0; j < 8; ++j) {
        const int row = r0 + ty * 8 + j;
        if (row < M_ITEMS) {
            float4 o;
            o.x = acc[j][0] + b4.x;
            o.y = acc[j][1] + b4.y;
            o.z = acc[j][2] + b4.z;
            o.w = acc[j][3] + b4.w;
            reinterpret_cast<float4*>(g_item)[(size_t)row * 32 + tx] = o;
        }
    }
}

// ---------------------------------------------------------------------------
// K2: per-item attention scalars a1[i], a2[i]. One warp per item row.
// ---------------------------------------------------------------------------
__global__ void __launch_bounds__(256) k_attvec(const float* __restrict__ Watt) {
    const int gwarp = (blockIdx.x * blockDim.x + threadIdx.x) >> 5;
    const int lane  = threadIdx.x & 31;
    if (gwarp >= M_ITEMS) return;

    const float4 v  = reinterpret_cast<const float4*>(g_item)[(size_t)gwarp * 32 + lane];
    const float4 w1 = reinterpret_cast<const float4*>(Watt)[lane];
    const float4 w2 = reinterpret_cast<const float4*>(Watt)[32 + lane];
    float d1 = v.x * w1.x + v.y * w1.y + v.z * w1.z + v.w * w1.w;
    float d2 = v.x * w2.x + v.y * w2.y + v.z * w2.z + v.w * w2.w;
#pragma unroll
    for (int o = 16; o; o >>= 1) {
        d1 += __shfl_xor_sync(0xFFFFFFFFu, d1, o);
        d2 += __shfl_xor_sync(0xFFFFFFFFu, d2, o);
    }
    if (lane == 0) {
        g_a1[gwarp] = d1;
        g_a2[gwarp] = d2;
    }
}

// ---------------------------------------------------------------------------
// K3: per-edge scores + segment boundary fill (edges sorted by src).
// ---------------------------------------------------------------------------
__global__ void __launch_bounds__(256) k_score(const float* __restrict__ batt) {
    const int e = blockIdx.x * blockDim.x + threadIdx.x;   // NE % 256 == 0
    const int2 p = g_edge[e];
    float att = g_a1[p.x] + g_a2[p.y] + batt[0];
    att = att > 0.f ? att : 0.2f * att;                    // leaky_relu(0.2)
    g_score[e] = __expf(att - 1.0f);

    // segment boundaries (race-free: disjoint ranges per thread)
    const int sprev = (e == 0) ? -1 : g_edge[e - 1].x;
    if (p.x != sprev) {
        for (int v = sprev + 1; v <= p.x; ++v) g_segstart[v] = e;
    }
    if (e == NE - 1) {
        for (int v = p.x + 1; v <= M_ITEMS; ++v) g_segstart[v] = NE;
    }
}

// ---------------------------------------------------------------------------
// K4: per-segment normalize + weighted gather-aggregate + sigmoid.
// One block per segment (deterministic block-local score sum, no atomics).
// ---------------------------------------------------------------------------
__global__ void __launch_bounds__(128) k_agg(float* __restrict__ out) {
    const int s   = blockIdx.x;
    const int tid = threadIdx.x;
    const int lo  = g_segstart[s];
    const int hi  = g_segstart[s + 1];

    __shared__ float s_w[128];
    __shared__ int   s_dst[128];
    __shared__ float s_red[4];

    // deterministic segment score sum
    float ssum = 0.f;
    for (int e = lo + tid; e < hi; e += 128) ssum += g_score[e];
#pragma unroll
    for (int o = 16; o; o >>= 1) ssum += __shfl_xor_sync(0xFFFFFFFFu, ssum, o);
    if ((tid & 31) == 0) s_red[tid >> 5] = ssum;
    __syncthreads();
    const float tot = s_red[0] + s_red[1] + s_red[2] + s_red[3];
    const float inv = (hi > lo) ? 1.f / tot : 0.f;

    float acc = 0.f;
    for (int base = lo; base < hi; base += 128) {
        const int cnt = min(128, hi - base);
        __syncthreads();   // protect s_w/s_dst reuse
        if (tid < cnt) {
            s_dst[tid] = g_edge[base + tid].y;
            s_w[tid]   = g_score[base + tid] * inv;
        }
        __syncthreads();
#pragma unroll 4
        for (int j = 0; j < cnt; ++j) {
            acc += s_w[j] * g_item[(size_t)s_dst[j] * 128 + tid];
        }
    }
    out[(size_t)s * 128 + tid] = 1.f / (1.f + __expf(-acc));
}

// ---------------------------------------------------------------------------
extern "C" void kernel_launch(void* const* d_in, const int* in_sizes, int n_in,
                              void* d_out, int out_size) {
    const float* emb  = (const float*)d_in[0];      // (20001, 128) f32
    const int*   edge = (const int*)d_in[1];        // (640000, 2) int (32- or 64-bit, sniffed)
    const float* W    = (const float*)d_in[2];      // (128, 128) f32
    const float* b    = (const float*)d_in[3];      // (128,) f32
    const float* Watt = (const float*)d_in[4];      // (256, 1) f32
    const float* batt = (const float*)d_in[5];      // (1,) f32
    float*       out  = (float*)d_out;              // (20001, 128) f32

    k_detect<<<1, 256>>>((const unsigned int*)edge);
    k_norm  <<<NE / 256, 256>>>(edge);
    k_gemm  <<<(M_ITEMS + 63) / 64, 256>>>(emb, W, b);
    k_attvec<<<(M_ITEMS * 32 + 255) / 256, 256>>>(Watt);
    k_score <<<NE / 256, 256>>>(batt);
    k_agg   <<<M_ITEMS, 128>>>(out);
}

// round 4
// speedup vs baseline: 1.2134x; 1.2134x over previous
#include <cuda_runtime.h>
#include <cuda_bf16.h>

// Problem constants (fixed by the reference)
#define M_ITEMS 20001      // emb rows / segments
#define EDIM    128
#define NE      640000     // edges (divisible by 256)

// Scratch (device globals: no runtime allocation allowed)
__device__ float g_item[M_ITEMS * EDIM];   // item_scaled = emb @ W + b
__device__ float g_a1[M_ITEMS];            // item_scaled . W_att[:128]
__device__ float g_a2[M_ITEMS];            // item_scaled . W_att[128:]
__device__ float g_score[NE];              // raw exp scores per edge
__device__ int   g_segstart[M_ITEMS + 1];  // segment boundaries (edges sorted by src)
__device__ int2  g_edge[NE];               // canonical (src, dst) pairs
__device__ int   g_is64;                   // 1 if edge input is int64-layout

// ---------------------------------------------------------------------------
// K0: sniff edge dtype. If int64, every odd 32-bit word is a zero high-half
// (values in [0, 20000]); if int32, odd words are random dst indices.
// ---------------------------------------------------------------------------
__global__ void k_detect(const unsigned int* __restrict__ w) {
    __shared__ unsigned int red[8];
    unsigned int v = 0;
    for (int k = threadIdx.x; k < 4096; k += 256) v |= w[2 * k + 1];
#pragma unroll
    for (int o = 16; o; o >>= 1) v |= __shfl_xor_sync(0xFFFFFFFFu, v, o);
    if ((threadIdx.x & 31) == 0) red[threadIdx.x >> 5] = v;
    __syncthreads();
    if (threadIdx.x == 0) {
        unsigned int t = 0;
#pragma unroll
        for (int j = 0; j < 8; ++j) t |= red[j];
        g_is64 = (t == 0) ? 1 : 0;
    }
}

// ---------------------------------------------------------------------------
// K1: item_scaled = emb_mat @ W_scale + b_scale   (20001 x 128 x 128, fp32)
// 64-row tile per block, 256 threads, 8x4 register micro-tile, K split in 2.
// Fused epilogue: per-row attention scalars a1/a2 via warp shuffle reduce.
// ---------------------------------------------------------------------------
__global__ void __launch_bounds__(256) k_gemm(const float* __restrict__ A,
                                              const float* __restrict__ W,
                                              const float* __restrict__ bias,
                                              const float* __restrict__ Watt) {
    __shared__ alignas(16) float sW[64 * 128];
    __shared__ alignas(16) float sA[64 * 64];   // transposed: sA[k][row]

    const int t  = threadIdx.x;
    const int tx = t & 31;          // column group: cols [4*tx, 4*tx+3]
    const int ty = t >> 5;          // row group: rows [8*ty, 8*ty+7]
    const int r0 = blockIdx.x * 64;

    float acc[8][4];
#pragma unroll
    for (int j = 0; j < 8; ++j)
#pragma unroll
        for (int c = 0; c < 4; ++c) acc[j][c] = 0.f;

    for (int kh = 0; kh < 2; ++kh) {
        const int k0 = kh * 64;
        // ---- load W[k0:k0+64][0:128] coalesced ----
        {
            const float4* Wg  = reinterpret_cast<const float4*>(W + (size_t)k0 * 128);
            float4*       sW4 = reinterpret_cast<float4*>(sW);
#pragma unroll
            for (int i = 0; i < 8; ++i) sW4[t + i * 256] = Wg[t + i * 256];
        }
        // ---- load A rows [r0, r0+64), k in [k0, k0+64), transposed ----
        {
            const int row  = t >> 2;               // 0..63
            const int kq   = (t & 3) * 16;         // 0,16,32,48
            const int grow = min(r0 + row, M_ITEMS - 1);
            const float4* Ag = reinterpret_cast<const float4*>(A + (size_t)grow * 128 + k0 + kq);
#pragma unroll
            for (int q = 0; q < 4; ++q) {
                float4 v = Ag[q];
                const int kk = kq + q * 4;
                sA[(kk + 0) * 64 + row] = v.x;
                sA[(kk + 1) * 64 + row] = v.y;
                sA[(kk + 2) * 64 + row] = v.z;
                sA[(kk + 3) * 64 + row] = v.w;
            }
        }
        __syncthreads();

        const float4* sW4 = reinterpret_cast<const float4*>(sW);
        const float4* sA4 = reinterpret_cast<const float4*>(sA);
#pragma unroll 8
        for (int k = 0; k < 64; ++k) {
            const float4 w4  = sW4[k * 32 + tx];
            const float4 a0  = sA4[k * 16 + ty * 2];
            const float4 a1v = sA4[k * 16 + ty * 2 + 1];
            const float a[8] = {a0.x, a0.y, a0.z, a0.w, a1v.x, a1v.y, a1v.z, a1v.w};
#pragma unroll
            for (int j = 0; j < 8; ++j) {
                acc[j][0] += a[j] * w4.x;
                acc[j][1] += a[j] * w4.y;
                acc[j][2] += a[j] * w4.z;
                acc[j][3] += a[j] * w4.w;
            }
        }
        __syncthreads();
    }

    const float4 b4 = reinterpret_cast<const float4*>(bias)[tx];
    const float4 w1 = reinterpret_cast<const float4*>(Watt)[tx];       // W_att[:128]
    const float4 w2 = reinterpret_cast<const float4*>(Watt)[32 + tx];  // W_att[128:]
#pragma unroll
    for (int j = 0; j < 8; ++j) {
        const int row = r0 + ty * 8 + j;
        float4 o;
        o.x = acc[j][0] + b4.x;
        o.y = acc[j][1] + b4.y;
        o.z = acc[j][2] + b4.z;
        o.w = acc[j][3] + b4.w;
        if (row < M_ITEMS)
            reinterpret_cast<float4*>(g_item)[(size_t)row * 32 + tx] = o;

        // fused attention scalars: reduce across the warp's 32 column groups
        float d1 = o.x * w1.x + o.y * w1.y + o.z * w1.z + o.w * w1.w;
        float d2 = o.x * w2.x + o.y * w2.y + o.z * w2.z + o.w * w2.w;
#pragma unroll
        for (int off = 16; off; off >>= 1) {
            d1 += __shfl_xor_sync(0xFFFFFFFFu, d1, off);
            d2 += __shfl_xor_sync(0xFFFFFFFFu, d2, off);
        }
        if (tx == 0 && row < M_ITEMS) {
            g_a1[row] = d1;
            g_a2[row] = d2;
        }
    }
}

// ---------------------------------------------------------------------------
// K2: fused edge pass — normalize edges, per-edge exp score, segment bounds.
// ---------------------------------------------------------------------------
__global__ void __launch_bounds__(256) k_edge(const int* __restrict__ ew,
                                              const float* __restrict__ batt) {
    const int e = blockIdx.x * blockDim.x + threadIdx.x;   // NE % 256 == 0
    const int is64 = g_is64;
    int2 p;
    if (is64) { p.x = ew[4 * e]; p.y = ew[4 * e + 2]; }
    else      { p.x = ew[2 * e]; p.y = ew[2 * e + 1]; }
    g_edge[e] = p;

    float att = g_a1[p.x] + g_a2[p.y] + batt[0];
    att = att > 0.f ? att : 0.2f * att;                    // leaky_relu(0.2)
    g_score[e] = __expf(att - 1.0f);

    // segment boundaries (race-free: disjoint ranges per thread)
    const int sprev = (e == 0) ? -1 : (is64 ? ew[4 * e - 4] : ew[2 * e - 2]);
    if (p.x != sprev) {
        for (int v = sprev + 1; v <= p.x; ++v) g_segstart[v] = e;
    }
    if (e == NE - 1) {
        for (int v = p.x + 1; v <= M_ITEMS; ++v) g_segstart[v] = NE;
    }
}

// ---------------------------------------------------------------------------
// K3: per-segment normalize + weighted gather-aggregate + sigmoid.
// One block per segment; warp-per-edge float4 gathers (LDG.128), weights
// staged in smem; deterministic fixed-order reductions (no atomics).
// ---------------------------------------------------------------------------
__global__ void __launch_bounds__(128) k_agg(float* __restrict__ out) {
    const int s    = blockIdx.x;
    const int tid  = threadIdx.x;
    const int wid  = tid >> 5;
    const int lane = tid & 31;
    const int lo   = g_segstart[s];
    const int hi   = g_segstart[s + 1];

    __shared__ float s_w[128];
    __shared__ int   s_dst[128];
    __shared__ float s_red[4];
    __shared__ alignas(16) float s_acc[4 * 128];

    // deterministic segment score sum
    float ssum = 0.f;
    for (int e = lo + tid; e < hi; e += 128) ssum += g_score[e];
#pragma unroll
    for (int o = 16; o; o >>= 1) ssum += __shfl_xor_sync(0xFFFFFFFFu, ssum, o);
    if (lane == 0) s_red[wid] = ssum;
    __syncthreads();
    const float tot = s_red[0] + s_red[1] + s_red[2] + s_red[3];
    const float inv = (hi > lo) ? 1.f / tot : 0.f;

    const float4* item4 = reinterpret_cast<const float4*>(g_item);
    float4 acc = make_float4(0.f, 0.f, 0.f, 0.f);

    for (int base = lo; base < hi; base += 128) {
        const int cnt = min(128, hi - base);
        __syncthreads();
        if (tid < cnt) {
            s_dst[tid] = g_edge[base + tid].y;
            s_w[tid]   = g_score[base + tid] * inv;
        }
        __syncthreads();
        // warp-per-edge gather: warp w handles edges j = w, w+4, w+8, ...
        int j = wid;
        for (; j + 8 <= cnt; j += 8) {              // 2 edges in flight (MLP=2)
            const float4 v0 = item4[(size_t)s_dst[j]     * 32 + lane];
            const float4 v1 = item4[(size_t)s_dst[j + 4] * 32 + lane];
            const float  c0 = s_w[j];
            const float  c1 = s_w[j + 4];
            acc.x += c0 * v0.x; acc.y += c0 * v0.y; acc.z += c0 * v0.z; acc.w += c0 * v0.w;
            acc.x += c1 * v1.x; acc.y += c1 * v1.y; acc.z += c1 * v1.z; acc.w += c1 * v1.w;
        }
        for (; j < cnt; j += 4) {                   // tail: covers ALL residues
            const float4 v0 = item4[(size_t)s_dst[j] * 32 + lane];
            const float  c0 = s_w[j];
            acc.x += c0 * v0.x; acc.y += c0 * v0.y; acc.z += c0 * v0.z; acc.w += c0 * v0.w;
        }
    }

    // cross-warp reduction (fixed order -> deterministic)
    reinterpret_cast<float4*>(s_acc)[wid * 32 + lane] = acc;
    __syncthreads();
    const float r = s_acc[0 * 128 + tid] + s_acc[1 * 128 + tid] +
                    s_acc[2 * 128 + tid] + s_acc[3 * 128 + tid];
    out[(size_t)s * 128 + tid] = 1.f / (1.f + __expf(-r));
}

// ---------------------------------------------------------------------------
extern "C" void kernel_launch(void* const* d_in, const int* in_sizes, int n_in,
                              void* d_out, int out_size) {
    const float* emb  = (const float*)d_in[0];      // (20001, 128) f32
    const int*   edge = (const int*)d_in[1];        // (640000, 2) int (32/64-bit, sniffed)
    const float* W    = (const float*)d_in[2];      // (128, 128) f32
    const float* b    = (const float*)d_in[3];      // (128,) f32
    const float* Watt = (const float*)d_in[4];      // (256, 1) f32
    const float* batt = (const float*)d_in[5];      // (1,) f32
    float*       out  = (float*)d_out;              // (20001, 128) f32

    k_detect<<<1, 256>>>((const unsigned int*)edge);
    k_gemm  <<<(M_ITEMS + 63) / 64, 256>>>(emb, W, b, Watt);
    k_edge  <<<NE / 256, 256>>>(edge, batt);
    k_agg   <<<M_ITEMS, 128>>>(out);
}

// round 5
// speedup vs baseline: 1.2634x; 1.0412x over previous
#include <cuda_runtime.h>
#include <cuda_bf16.h>

// Problem constants (fixed by the reference)
#define M_ITEMS 20001      // emb rows / segments
#define EDIM    128
#define NE      640000     // edges (divisible by 256)

// Scratch (device globals: no runtime allocation allowed)
__device__ float g_item[M_ITEMS * EDIM];   // item_scaled = emb @ W + b
__device__ float g_a1[M_ITEMS];            // item_scaled . W_att[:128]
__device__ float g_a2[M_ITEMS];            // item_scaled . W_att[128:]
__device__ float g_score[NE];              // raw exp scores per edge
__device__ int   g_segstart[M_ITEMS + 1];  // segment boundaries (edges sorted by src)
__device__ int2  g_edge[NE];               // canonical (src, dst) pairs
__device__ int   g_is64;                   // 1 if edge input is int64-layout

// ---------------------------------------------------------------------------
// K0: sniff edge dtype. If int64, every odd 32-bit word is a zero high-half
// (values in [0, 20000]); if int32, odd words are random dst indices.
// ---------------------------------------------------------------------------
__global__ void k_detect(const unsigned int* __restrict__ w) {
    __shared__ unsigned int red[8];
    unsigned int v = 0;
    for (int k = threadIdx.x; k < 4096; k += 256) v |= w[2 * k + 1];
#pragma unroll
    for (int o = 16; o; o >>= 1) v |= __shfl_xor_sync(0xFFFFFFFFu, v, o);
    if ((threadIdx.x & 31) == 0) red[threadIdx.x >> 5] = v;
    __syncthreads();
    if (threadIdx.x == 0) {
        unsigned int t = 0;
#pragma unroll
        for (int j = 0; j < 8; ++j) t |= red[j];
        g_is64 = (t == 0) ? 1 : 0;
    }
}

// ---------------------------------------------------------------------------
// K1: item_scaled = emb_mat @ W_scale + b_scale   (20001 x 128 x 128, fp32)
// 64-row tile per block, 256 threads, 8x4 register micro-tile, K split in 2.
// Fused epilogue: per-row attention scalars a1/a2 via warp shuffle reduce.
// ---------------------------------------------------------------------------
__global__ void __launch_bounds__(256) k_gemm(const float* __restrict__ A,
                                              const float* __restrict__ W,
                                              const float* __restrict__ bias,
                                              const float* __restrict__ Watt) {
    __shared__ alignas(16) float sW[64 * 128];
    __shared__ alignas(16) float sA[64 * 64];   // transposed: sA[k][row]

    const int t  = threadIdx.x;
    const int tx = t & 31;          // column group: cols [4*tx, 4*tx+3]
    const int ty = t >> 5;          // row group: rows [8*ty, 8*ty+7]
    const int r0 = blockIdx.x * 64;

    float acc[8][4];
#pragma unroll
    for (int j = 0; j < 8; ++j)
#pragma unroll
        for (int c = 0; c < 4; ++c) acc[j][c] = 0.f;

    for (int kh = 0; kh < 2; ++kh) {
        const int k0 = kh * 64;
        // ---- load W[k0:k0+64][0:128] coalesced ----
        {
            const float4* Wg  = reinterpret_cast<const float4*>(W + (size_t)k0 * 128);
            float4*       sW4 = reinterpret_cast<float4*>(sW);
#pragma unroll
            for (int i = 0; i < 8; ++i) sW4[t + i * 256] = Wg[t + i * 256];
        }
        // ---- load A rows [r0, r0+64), k in [k0, k0+64), transposed ----
        {
            const int row  = t >> 2;               // 0..63
            const int kq   = (t & 3) * 16;         // 0,16,32,48
            const int grow = min(r0 + row, M_ITEMS - 1);
            const float4* Ag = reinterpret_cast<const float4*>(A + (size_t)grow * 128 + k0 + kq);
#pragma unroll
            for (int q = 0; q < 4; ++q) {
                float4 v = Ag[q];
                const int kk = kq + q * 4;
                sA[(kk + 0) * 64 + row] = v.x;
                sA[(kk + 1) * 64 + row] = v.y;
                sA[(kk + 2) * 64 + row] = v.z;
                sA[(kk + 3) * 64 + row] = v.w;
            }
        }
        __syncthreads();

        const float4* sW4 = reinterpret_cast<const float4*>(sW);
        const float4* sA4 = reinterpret_cast<const float4*>(sA);
#pragma unroll 8
        for (int k = 0; k < 64; ++k) {
            const float4 w4  = sW4[k * 32 + tx];
            const float4 a0  = sA4[k * 16 + ty * 2];
            const float4 a1v = sA4[k * 16 + ty * 2 + 1];
            const float a[8] = {a0.x, a0.y, a0.z, a0.w, a1v.x, a1v.y, a1v.z, a1v.w};
#pragma unroll
            for (int j = 0; j < 8; ++j) {
                acc[j][0] += a[j] * w4.x;
                acc[j][1] += a[j] * w4.y;
                acc[j][2] += a[j] * w4.z;
                acc[j][3] += a[j] * w4.w;
            }
        }
        __syncthreads();
    }

    const float4 b4 = reinterpret_cast<const float4*>(bias)[tx];
    const float4 w1 = reinterpret_cast<const float4*>(Watt)[tx];       // W_att[:128]
    const float4 w2 = reinterpret_cast<const float4*>(Watt)[32 + tx];  // W_att[128:]
#pragma unroll
    for (int j = 0; j < 8; ++j) {
        const int row = r0 + ty * 8 + j;
        float4 o;
        o.x = acc[j][0] + b4.x;
        o.y = acc[j][1] + b4.y;
        o.z = acc[j][2] + b4.z;
        o.w = acc[j][3] + b4.w;
        if (row < M_ITEMS)
            reinterpret_cast<float4*>(g_item)[(size_t)row * 32 + tx] = o;

        // fused attention scalars: reduce across the warp's 32 column groups
        float d1 = o.x * w1.x + o.y * w1.y + o.z * w1.z + o.w * w1.w;
        float d2 = o.x * w2.x + o.y * w2.y + o.z * w2.z + o.w * w2.w;
#pragma unroll
        for (int off = 16; off; off >>= 1) {
            d1 += __shfl_xor_sync(0xFFFFFFFFu, d1, off);
            d2 += __shfl_xor_sync(0xFFFFFFFFu, d2, off);
        }
        if (tx == 0 && row < M_ITEMS) {
            g_a1[row] = d1;
            g_a2[row] = d2;
        }
    }
}

// ---------------------------------------------------------------------------
// K2: fused edge pass — normalize edges, per-edge exp score, segment bounds.
// ---------------------------------------------------------------------------
__global__ void __launch_bounds__(256) k_edge(const int* __restrict__ ew,
                                              const float* __restrict__ batt) {
    const int e = blockIdx.x * blockDim.x + threadIdx.x;   // NE % 256 == 0
    const int is64 = g_is64;
    int2 p;
    if (is64) { p.x = ew[4 * e]; p.y = ew[4 * e + 2]; }
    else      { p.x = ew[2 * e]; p.y = ew[2 * e + 1]; }
    g_edge[e] = p;

    float att = g_a1[p.x] + g_a2[p.y] + batt[0];
    att = att > 0.f ? att : 0.2f * att;                    // leaky_relu(0.2)
    g_score[e] = __expf(att - 1.0f);

    // segment boundaries (race-free: disjoint ranges per thread)
    const int sprev = (e == 0) ? -1 : (is64 ? ew[4 * e - 4] : ew[2 * e - 2]);
    if (p.x != sprev) {
        for (int v = sprev + 1; v <= p.x; ++v) g_segstart[v] = e;
    }
    if (e == NE - 1) {
        for (int v = p.x + 1; v <= M_ITEMS; ++v) g_segstart[v] = NE;
    }
}

// ---------------------------------------------------------------------------
// K3: warp-per-segment gather-aggregate.
// Single pass: accumulate unnormalized sum and score total together, scale
// by 1/total at the end (softmax normalization commutes with the weighted
// sum). Lane l owns output columns [4l, 4l+4) -> one LDG.128 per edge.
// Edge (dst, score) loaded coalesced into registers, broadcast via shuffle.
// No shared memory, no block barriers; fixed orders -> deterministic.
// ---------------------------------------------------------------------------
__global__ void __launch_bounds__(256) k_agg(float* __restrict__ out) {
    const int seg  = blockIdx.x * 8 + (threadIdx.x >> 5);
    const int lane = threadIdx.x & 31;
    if (seg >= M_ITEMS) return;

    const int lo = g_segstart[seg];
    const int hi = g_segstart[seg + 1];

    const float4* item4 = reinterpret_cast<const float4*>(g_item);
    float4 acc = make_float4(0.f, 0.f, 0.f, 0.f);
    float  ssum = 0.f;

    for (int base = lo; base < hi; base += 32) {
        const int cnt = min(32, hi - base);
        int   dst = 0;
        float sc  = 0.f;
        if (lane < cnt) {
            dst = g_edge[base + lane].y;
            sc  = g_score[base + lane];
        }
        ssum += sc;   // per-lane partial, fixed order

        int j = 0;
        for (; j + 4 <= cnt; j += 4) {   // 4 gathers in flight (MLP=4)
            const int   d0 = __shfl_sync(0xFFFFFFFFu, dst, j);
            const int   d1 = __shfl_sync(0xFFFFFFFFu, dst, j + 1);
            const int   d2 = __shfl_sync(0xFFFFFFFFu, dst, j + 2);
            const int   d3 = __shfl_sync(0xFFFFFFFFu, dst, j + 3);
            const float c0 = __shfl_sync(0xFFFFFFFFu, sc, j);
            const float c1 = __shfl_sync(0xFFFFFFFFu, sc, j + 1);
            const float c2 = __shfl_sync(0xFFFFFFFFu, sc, j + 2);
            const float c3 = __shfl_sync(0xFFFFFFFFu, sc, j + 3);
            const float4 v0 = item4[(size_t)d0 * 32 + lane];
            const float4 v1 = item4[(size_t)d1 * 32 + lane];
            const float4 v2 = item4[(size_t)d2 * 32 + lane];
            const float4 v3 = item4[(size_t)d3 * 32 + lane];
            acc.x += c0 * v0.x; acc.y += c0 * v0.y; acc.z += c0 * v0.z; acc.w += c0 * v0.w;
            acc.x += c1 * v1.x; acc.y += c1 * v1.y; acc.z += c1 * v1.z; acc.w += c1 * v1.w;
            acc.x += c2 * v2.x; acc.y += c2 * v2.y; acc.z += c2 * v2.z; acc.w += c2 * v2.w;
            acc.x += c3 * v3.x; acc.y += c3 * v3.y; acc.z += c3 * v3.z; acc.w += c3 * v3.w;
        }
        for (; j < cnt; ++j) {
            const int   d0 = __shfl_sync(0xFFFFFFFFu, dst, j);
            const float c0 = __shfl_sync(0xFFFFFFFFu, sc, j);
            const float4 v0 = item4[(size_t)d0 * 32 + lane];
            acc.x += c0 * v0.x; acc.y += c0 * v0.y; acc.z += c0 * v0.z; acc.w += c0 * v0.w;
        }
    }

    // warp-reduce score total (fixed order -> deterministic)
#pragma unroll
    for (int o = 16; o; o >>= 1) ssum += __shfl_xor_sync(0xFFFFFFFFu, ssum, o);
    const float inv = (hi > lo) ? 1.f / ssum : 0.f;

    float4 r;
    r.x = 1.f / (1.f + __expf(-acc.x * inv));
    r.y = 1.f / (1.f + __expf(-acc.y * inv));
    r.z = 1.f / (1.f + __expf(-acc.z * inv));
    r.w = 1.f / (1.f + __expf(-acc.w * inv));
    reinterpret_cast<float4*>(out)[(size_t)seg * 32 + lane] = r;
}

// ---------------------------------------------------------------------------
extern "C" void kernel_launch(void* const* d_in, const int* in_sizes, int n_in,
                              void* d_out, int out_size) {
    const float* emb  = (const float*)d_in[0];      // (20001, 128) f32
    const int*   edge = (const int*)d_in[1];        // (640000, 2) int (32/64-bit, sniffed)
    const float* W    = (const float*)d_in[2];      // (128, 128) f32
    const float* b    = (const float*)d_in[3];      // (128,) f32
    const float* Watt = (const float*)d_in[4];      // (256, 1) f32
    const float* batt = (const float*)d_in[5];      // (1,) f32
    float*       out  = (float*)d_out;              // (20001, 128) f32

    k_detect<<<1, 256>>>((const unsigned int*)edge);
    k_gemm  <<<(M_ITEMS + 63) / 64, 256>>>(emb, W, b, Watt);
    k_edge  <<<NE / 256, 256>>>(edge, batt);
    k_agg   <<<(M_ITEMS + 7) / 8, 256>>>(out);
}

// round 6
// speedup vs baseline: 1.3599x; 1.0764x over previous
#include <cuda_runtime.h>
#include <cuda_bf16.h>

// Problem constants (fixed by the reference)
#define M_ITEMS 20001      // emb rows / segments
#define EDIM    128
#define NE      640000     // edges (divisible by 256)

// Scratch (device globals: no runtime allocation allowed)
__device__ __nv_bfloat16 g_itemh[M_ITEMS * EDIM]; // item_scaled in bf16 (gather table)
__device__ float g_a1[M_ITEMS];            // item_scaled . W_att[:128]  (fp32 exact)
__device__ float g_a2[M_ITEMS];            // item_scaled . W_att[128:]  (fp32 exact)
__device__ int2  g_ds[NE];                 // packed (dst, score_bits) per edge
__device__ int   g_segstart[M_ITEMS + 1];  // segment boundaries (edges sorted by src)
__device__ int   g_is64;                   // 1 if edge input is int64-layout

// ---------------------------------------------------------------------------
// K0: sniff edge dtype. If int64, every odd 32-bit word is a zero high-half
// (values in [0, 20000]); if int32, odd words are random dst indices.
// ---------------------------------------------------------------------------
__global__ void k_detect(const unsigned int* __restrict__ w) {
    __shared__ unsigned int red[8];
    unsigned int v = 0;
    for (int k = threadIdx.x; k < 4096; k += 256) v |= w[2 * k + 1];
#pragma unroll
    for (int o = 16; o; o >>= 1) v |= __shfl_xor_sync(0xFFFFFFFFu, v, o);
    if ((threadIdx.x & 31) == 0) red[threadIdx.x >> 5] = v;
    __syncthreads();
    if (threadIdx.x == 0) {
        unsigned int t = 0;
#pragma unroll
        for (int j = 0; j < 8; ++j) t |= red[j];
        g_is64 = (t == 0) ? 1 : 0;
    }
}

// ---------------------------------------------------------------------------
// K1: item_scaled = emb_mat @ W_scale + b_scale   (20001 x 128 x 128, fp32)
// 64-row tile per block, 256 threads, 8x4 register micro-tile, K split in 2.
// Epilogue: bf16 store of item rows + fp32 attention scalars a1/a2.
// ---------------------------------------------------------------------------
__global__ void __launch_bounds__(256) k_gemm(const float* __restrict__ A,
                                              const float* __restrict__ W,
                                              const float* __restrict__ bias,
                                              const float* __restrict__ Watt) {
    __shared__ alignas(16) float sW[64 * 128];
    __shared__ alignas(16) float sA[64 * 64];   // transposed: sA[k][row]

    const int t  = threadIdx.x;
    const int tx = t & 31;          // column group: cols [4*tx, 4*tx+3]
    const int ty = t >> 5;          // row group: rows [8*ty, 8*ty+7]
    const int r0 = blockIdx.x * 64;

    float acc[8][4];
#pragma unroll
    for (int j = 0; j < 8; ++j)
#pragma unroll
        for (int c = 0; c < 4; ++c) acc[j][c] = 0.f;

    for (int kh = 0; kh < 2; ++kh) {
        const int k0 = kh * 64;
        // ---- load W[k0:k0+64][0:128] coalesced ----
        {
            const float4* Wg  = reinterpret_cast<const float4*>(W + (size_t)k0 * 128);
            float4*       sW4 = reinterpret_cast<float4*>(sW);
#pragma unroll
            for (int i = 0; i < 8; ++i) sW4[t + i * 256] = Wg[t + i * 256];
        }
        // ---- load A rows [r0, r0+64), k in [k0, k0+64), transposed ----
        {
            const int row  = t >> 2;               // 0..63
            const int kq   = (t & 3) * 16;         // 0,16,32,48
            const int grow = min(r0 + row, M_ITEMS - 1);
            const float4* Ag = reinterpret_cast<const float4*>(A + (size_t)grow * 128 + k0 + kq);
#pragma unroll
            for (int q = 0; q < 4; ++q) {
                float4 v = Ag[q];
                const int kk = kq + q * 4;
                sA[(kk + 0) * 64 + row] = v.x;
                sA[(kk + 1) * 64 + row] = v.y;
                sA[(kk + 2) * 64 + row] = v.z;
                sA[(kk + 3) * 64 + row] = v.w;
            }
        }
        __syncthreads();

        const float4* sW4 = reinterpret_cast<const float4*>(sW);
        const float4* sA4 = reinterpret_cast<const float4*>(sA);
#pragma unroll 8
        for (int k = 0; k < 64; ++k) {
            const float4 w4  = sW4[k * 32 + tx];
            const float4 a0  = sA4[k * 16 + ty * 2];
            const float4 a1v = sA4[k * 16 + ty * 2 + 1];
            const float a[8] = {a0.x, a0.y, a0.z, a0.w, a1v.x, a1v.y, a1v.z, a1v.w};
#pragma unroll
            for (int j = 0; j < 8; ++j) {
                acc[j][0] += a[j] * w4.x;
                acc[j][1] += a[j] * w4.y;
                acc[j][2] += a[j] * w4.z;
                acc[j][3] += a[j] * w4.w;
            }
        }
        __syncthreads();
    }

    const float4 b4 = reinterpret_cast<const float4*>(bias)[tx];
    const float4 w1 = reinterpret_cast<const float4*>(Watt)[tx];       // W_att[:128]
    const float4 w2 = reinterpret_cast<const float4*>(Watt)[32 + tx];  // W_att[128:]
#pragma unroll
    for (int j = 0; j < 8; ++j) {
        const int row = r0 + ty * 8 + j;
        float4 o;
        o.x = acc[j][0] + b4.x;
        o.y = acc[j][1] + b4.y;
        o.z = acc[j][2] + b4.z;
        o.w = acc[j][3] + b4.w;
        if (row < M_ITEMS) {
            // bf16 row for the gather table (halves k_agg traffic)
            __nv_bfloat162 h0 = __float22bfloat162_rn(make_float2(o.x, o.y));
            __nv_bfloat162 h1 = __float22bfloat162_rn(make_float2(o.z, o.w));
            uint2 pk;
            pk.x = *reinterpret_cast<unsigned int*>(&h0);
            pk.y = *reinterpret_cast<unsigned int*>(&h1);
            reinterpret_cast<uint2*>(g_itemh)[(size_t)row * 32 + tx] = pk;
        }

        // fused attention scalars (fp32 exact): reduce across warp columns
        float d1 = o.x * w1.x + o.y * w1.y + o.z * w1.z + o.w * w1.w;
        float d2 = o.x * w2.x + o.y * w2.y + o.z * w2.z + o.w * w2.w;
#pragma unroll
        for (int off = 16; off; off >>= 1) {
            d1 += __shfl_xor_sync(0xFFFFFFFFu, d1, off);
            d2 += __shfl_xor_sync(0xFFFFFFFFu, d2, off);
        }
        if (tx == 0 && row < M_ITEMS) {
            g_a1[row] = d1;
            g_a2[row] = d2;
        }
    }
}

// ---------------------------------------------------------------------------
// K2: fused edge pass — per-edge exp score packed with dst, segment bounds.
// ---------------------------------------------------------------------------
__global__ void __launch_bounds__(256) k_edge(const int* __restrict__ ew,
                                              const float* __restrict__ batt) {
    const int e = blockIdx.x * blockDim.x + threadIdx.x;   // NE % 256 == 0
    const int is64 = g_is64;
    int src, dst;
    if (is64) { src = ew[4 * e]; dst = ew[4 * e + 2]; }
    else      { src = ew[2 * e]; dst = ew[2 * e + 1]; }

    float att = g_a1[src] + g_a2[dst] + batt[0];
    att = att > 0.f ? att : 0.2f * att;                    // leaky_relu(0.2)
    const float sc = __expf(att - 1.0f);
    g_ds[e] = make_int2(dst, __float_as_int(sc));

    // segment boundaries (race-free: disjoint ranges per thread)
    const int sprev = (e == 0) ? -1 : (is64 ? ew[4 * e - 4] : ew[2 * e - 2]);
    if (src != sprev) {
        for (int v = sprev + 1; v <= src; ++v) g_segstart[v] = e;
    }
    if (e == NE - 1) {
        for (int v = src + 1; v <= M_ITEMS; ++v) g_segstart[v] = NE;
    }
}

// ---------------------------------------------------------------------------
// K3: warp-per-segment gather-aggregate over the bf16 item table.
// Single pass: unnormalized weighted sum + score total, post-scaled
// (softmax normalization commutes). Lane l owns cols [4l, 4l+4) -> LDG.64
// per edge. 8 edges in flight (MLP=8). No smem/barriers; fixed reduction
// orders -> deterministic.
// ---------------------------------------------------------------------------
__global__ void __launch_bounds__(256) k_agg(float* __restrict__ out) {
    const int seg  = blockIdx.x * 8 + (threadIdx.x >> 5);
    const int lane = threadIdx.x & 31;
    if (seg >= M_ITEMS) return;

    const int lo = g_segstart[seg];
    const int hi = g_segstart[seg + 1];

    const uint2* itemh = reinterpret_cast<const uint2*>(g_itemh);   // row = 32 uint2
    float4 acc = make_float4(0.f, 0.f, 0.f, 0.f);
    float  ssum = 0.f;

    for (int base = lo; base < hi; base += 32) {
        const int cnt = min(32, hi - base);
        int   dst = 0;
        float sc  = 0.f;
        if (lane < cnt) {
            const int2 ds = g_ds[base + lane];
            dst = ds.x;
            sc  = __int_as_float(ds.y);
        }
        ssum += sc;   // per-lane partial, fixed order

        int j = 0;
        for (; j + 8 <= cnt; j += 8) {   // 8 gathers in flight
            int d[8]; float c[8]; uint2 v[8];
#pragma unroll
            for (int u = 0; u < 8; ++u) {
                d[u] = __shfl_sync(0xFFFFFFFFu, dst, j + u);
                c[u] = __shfl_sync(0xFFFFFFFFu, sc,  j + u);
            }
#pragma unroll
            for (int u = 0; u < 8; ++u) v[u] = itemh[(size_t)d[u] * 32 + lane];
#pragma unroll
            for (int u = 0; u < 8; ++u) {
                const float2 p0 = __bfloat1622float2(*reinterpret_cast<const __nv_bfloat162*>(&v[u].x));
                const float2 p1 = __bfloat1622float2(*reinterpret_cast<const __nv_bfloat162*>(&v[u].y));
                acc.x += c[u] * p0.x; acc.y += c[u] * p0.y;
                acc.z += c[u] * p1.x; acc.w += c[u] * p1.y;
            }
        }
        for (; j < cnt; ++j) {           // tail: all residues
            const int   d0 = __shfl_sync(0xFFFFFFFFu, dst, j);
            const float c0 = __shfl_sync(0xFFFFFFFFu, sc,  j);
            const uint2 v0 = itemh[(size_t)d0 * 32 + lane];
            const float2 p0 = __bfloat1622float2(*reinterpret_cast<const __nv_bfloat162*>(&v0.x));
            const float2 p1 = __bfloat1622float2(*reinterpret_cast<const __nv_bfloat162*>(&v0.y));
            acc.x += c0 * p0.x; acc.y += c0 * p0.y;
            acc.z += c0 * p1.x; acc.w += c0 * p1.y;
        }
    }

    // warp-reduce score total (fixed order -> deterministic)
#pragma unroll
    for (int o = 16; o; o >>= 1) ssum += __shfl_xor_sync(0xFFFFFFFFu, ssum, o);
    const float inv = (hi > lo) ? 1.f / ssum : 0.f;

    float4 r;
    r.x = 1.f / (1.f + __expf(-acc.x * inv));
    r.y = 1.f / (1.f + __expf(-acc.y * inv));
    r.z = 1.f / (1.f + __expf(-acc.z * inv));
    r.w = 1.f / (1.f + __expf(-acc.w * inv));
    reinterpret_cast<float4*>(out)[(size_t)seg * 32 + lane] = r;
}

// ---------------------------------------------------------------------------
extern "C" void kernel_launch(void* const* d_in, const int* in_sizes, int n_in,
                              void* d_out, int out_size) {
    const float* emb  = (const float*)d_in[0];      // (20001, 128) f32
    const int*   edge = (const int*)d_in[1];        // (640000, 2) int (32/64-bit, sniffed)
    const float* W    = (const float*)d_in[2];      // (128, 128) f32
    const float* b    = (const float*)d_in[3];      // (128,) f32
    const float* Watt = (const float*)d_in[4];      // (256, 1) f32
    const float* batt = (const float*)d_in[5];      // (1,) f32
    float*       out  = (float*)d_out;              // (20001, 128) f32

    k_detect<<<1, 256>>>((const unsigned int*)edge);
    k_gemm  <<<(M_ITEMS + 63) / 64, 256>>>(emb, W, b, Watt);
    k_edge  <<<NE / 256, 256>>>(edge, batt);
    k_agg   <<<(M_ITEMS + 7) / 8, 256>>>(out);
}

// round 7
// speedup vs baseline: 1.4115x; 1.0379x over previous
#include <cuda_runtime.h>
#include <cuda_bf16.h>

// Problem constants (fixed by the reference)
#define M_ITEMS 20001      // emb rows / segments
#define EDIM    128
#define NE      640000     // edges (divisible by 256)

// Scratch (device globals: no runtime allocation allowed)
__device__ __nv_bfloat16 g_itemh[M_ITEMS * EDIM]; // item_scaled in bf16 (gather table)
__device__ float g_a1[M_ITEMS];            // item_scaled . W_att[:128]  (fp32 exact)
__device__ float g_a2[M_ITEMS];            // item_scaled . W_att[128:]  (fp32 exact)
__device__ int2  g_ds[NE];                 // packed (dst, score_bits) per edge
__device__ int   g_segstart[M_ITEMS + 1];  // segment boundaries (edges sorted by src)

// ---------------------------------------------------------------------------
// K1: item_scaled = emb_mat @ W_scale + b_scale   (20001 x 128 x 128, fp32)
// 64-row tile per block, 256 threads, 8x4 register micro-tile, K split in 2.
// Epilogue: bf16 store of item rows + fp32 attention scalars a1/a2.
// ---------------------------------------------------------------------------
__global__ void __launch_bounds__(256) k_gemm(const float* __restrict__ A,
                                              const float* __restrict__ W,
                                              const float* __restrict__ bias,
                                              const float* __restrict__ Watt) {
    __shared__ alignas(16) float sW[64 * 128];
    __shared__ alignas(16) float sA[64 * 64];   // transposed: sA[k][row]

    const int t  = threadIdx.x;
    const int tx = t & 31;          // column group: cols [4*tx, 4*tx+3]
    const int ty = t >> 5;          // row group: rows [8*ty, 8*ty+7]
    const int r0 = blockIdx.x * 64;

    float acc[8][4];
#pragma unroll
    for (int j = 0; j < 8; ++j)
#pragma unroll
        for (int c = 0; c < 4; ++c) acc[j][c] = 0.f;

    for (int kh = 0; kh < 2; ++kh) {
        const int k0 = kh * 64;
        // ---- load W[k0:k0+64][0:128] coalesced ----
        {
            const float4* Wg  = reinterpret_cast<const float4*>(W + (size_t)k0 * 128);
            float4*       sW4 = reinterpret_cast<float4*>(sW);
#pragma unroll
            for (int i = 0; i < 8; ++i) sW4[t + i * 256] = Wg[t + i * 256];
        }
        // ---- load A rows [r0, r0+64), k in [k0, k0+64), transposed ----
        {
            const int row  = t >> 2;               // 0..63
            const int kq   = (t & 3) * 16;         // 0,16,32,48
            const int grow = min(r0 + row, M_ITEMS - 1);
            const float4* Ag = reinterpret_cast<const float4*>(A + (size_t)grow * 128 + k0 + kq);
#pragma unroll
            for (int q = 0; q < 4; ++q) {
                float4 v = Ag[q];
                const int kk = kq + q * 4;
                sA[(kk + 0) * 64 + row] = v.x;
                sA[(kk + 1) * 64 + row] = v.y;
                sA[(kk + 2) * 64 + row] = v.z;
                sA[(kk + 3) * 64 + row] = v.w;
            }
        }
        __syncthreads();

        const float4* sW4 = reinterpret_cast<const float4*>(sW);
        const float4* sA4 = reinterpret_cast<const float4*>(sA);
#pragma unroll 8
        for (int k = 0; k < 64; ++k) {
            const float4 w4  = sW4[k * 32 + tx];
            const float4 a0  = sA4[k * 16 + ty * 2];
            const float4 a1v = sA4[k * 16 + ty * 2 + 1];
            const float a[8] = {a0.x, a0.y, a0.z, a0.w, a1v.x, a1v.y, a1v.z, a1v.w};
#pragma unroll
            for (int j = 0; j < 8; ++j) {
                acc[j][0] += a[j] * w4.x;
                acc[j][1] += a[j] * w4.y;
                acc[j][2] += a[j] * w4.z;
                acc[j][3] += a[j] * w4.w;
            }
        }
        __syncthreads();
    }

    const float4 b4 = reinterpret_cast<const float4*>(bias)[tx];
    const float4 w1 = reinterpret_cast<const float4*>(Watt)[tx];       // W_att[:128]
    const float4 w2 = reinterpret_cast<const float4*>(Watt)[32 + tx];  // W_att[128:]
#pragma unroll
    for (int j = 0; j < 8; ++j) {
        const int row = r0 + ty * 8 + j;
        float4 o;
        o.x = acc[j][0] + b4.x;
        o.y = acc[j][1] + b4.y;
        o.z = acc[j][2] + b4.z;
        o.w = acc[j][3] + b4.w;
        if (row < M_ITEMS) {
            // bf16 row for the gather table (halves k_agg traffic)
            __nv_bfloat162 h0 = __float22bfloat162_rn(make_float2(o.x, o.y));
            __nv_bfloat162 h1 = __float22bfloat162_rn(make_float2(o.z, o.w));
            uint2 pk;
            pk.x = *reinterpret_cast<unsigned int*>(&h0);
            pk.y = *reinterpret_cast<unsigned int*>(&h1);
            reinterpret_cast<uint2*>(g_itemh)[(size_t)row * 32 + tx] = pk;
        }

        // fused attention scalars (fp32 exact): reduce across warp columns
        float d1 = o.x * w1.x + o.y * w1.y + o.z * w1.z + o.w * w1.w;
        float d2 = o.x * w2.x + o.y * w2.y + o.z * w2.z + o.w * w2.w;
#pragma unroll
        for (int off = 16; off; off >>= 1) {
            d1 += __shfl_xor_sync(0xFFFFFFFFu, d1, off);
            d2 += __shfl_xor_sync(0xFFFFFFFFu, d2, off);
        }
        if (tx == 0 && row < M_ITEMS) {
            g_a1[row] = d1;
            g_a2[row] = d2;
        }
    }
}

// ---------------------------------------------------------------------------
// K2: fused edge pass with per-block dtype sniff.
// If the edge tensor is int64, every odd 32-bit word in this block's window
// is a zero high-half; if int32, odd words are dst indices (never all zero
// over 256 random edges). In the int32 case the sniffed word IS dst.
// ---------------------------------------------------------------------------
__global__ void __launch_bounds__(256) k_edge(const int* __restrict__ ew,
                                              const float* __restrict__ batt) {
    __shared__ unsigned int s_or[8];
    const int e    = blockIdx.x * 256 + threadIdx.x;   // NE % 256 == 0
    const int lane = threadIdx.x & 31;

    const unsigned int odd = ((const unsigned int*)ew)[2 * e + 1];
    unsigned int v = odd;
#pragma unroll
    for (int o = 16; o; o >>= 1) v |= __shfl_xor_sync(0xFFFFFFFFu, v, o);
    if (lane == 0) s_or[threadIdx.x >> 5] = v;
    __syncthreads();
    const unsigned int t = s_or[0] | s_or[1] | s_or[2] | s_or[3] |
                           s_or[4] | s_or[5] | s_or[6] | s_or[7];
    const bool is64 = (t == 0u);

    int src, dst;
    if (is64) { src = ew[4 * e]; dst = ew[4 * e + 2]; }
    else      { src = ew[2 * e]; dst = (int)odd; }

    float att = g_a1[src] + g_a2[dst] + batt[0];
    att = att > 0.f ? att : 0.2f * att;                    // leaky_relu(0.2)
    const float sc = __expf(att - 1.0f);
    g_ds[e] = make_int2(dst, __float_as_int(sc));

    // segment boundaries (race-free: disjoint ranges per thread)
    const int sprev = (e == 0) ? -1 : (is64 ? ew[4 * e - 4] : ew[2 * e - 2]);
    if (src != sprev) {
        for (int q = sprev + 1; q <= src; ++q) g_segstart[q] = e;
    }
    if (e == NE - 1) {
        for (int q = src + 1; q <= M_ITEMS; ++q) g_segstart[q] = NE;
    }
}

// ---------------------------------------------------------------------------
// K3: warp-per-segment gather-aggregate over the bf16 item table.
// Block = 64 (2 segments) to minimize intra-block straggle. Uniform 16-deep
// load batches: padded slots carry (dst=0, sc=0) from staging, so they add
// nothing and hit L1 (row 0 stays hot) -> no serial tail loop, 16 loads in
// flight per warp. Softmax normalization post-scaled. Fixed reduction
// orders -> deterministic.
// ---------------------------------------------------------------------------
__global__ void __launch_bounds__(64) k_agg(float* __restrict__ out) {
    const int seg  = blockIdx.x * 2 + (threadIdx.x >> 5);
    const int lane = threadIdx.x & 31;
    if (seg >= M_ITEMS) return;

    const int lo = __ldg(&g_segstart[seg]);
    const int hi = __ldg(&g_segstart[seg + 1]);

    const uint2* itemh = reinterpret_cast<const uint2*>(g_itemh);   // row = 32 uint2
    float4 acc = make_float4(0.f, 0.f, 0.f, 0.f);
    float  ssum = 0.f;

    for (int base = lo; base < hi; base += 32) {
        const int cnt = min(32, hi - base);
        int   dst = 0;
        float sc  = 0.f;
        if (lane < cnt) {
            const int2 ds = g_ds[base + lane];
            dst = ds.x;
            sc  = __int_as_float(ds.y);
        }
        ssum += sc;   // per-lane partial, fixed order

        for (int j = 0; j < cnt; j += 16) {   // 16 gathers in flight; tail zero-padded
            int d[16]; float c[16]; uint2 v[16];
#pragma unroll
            for (int u = 0; u < 16; ++u) {
                d[u] = __shfl_sync(0xFFFFFFFFu, dst, j + u);  // padded slots -> 0
                c[u] = __shfl_sync(0xFFFFFFFFu, sc,  j + u);  // padded slots -> 0.0
            }
#pragma unroll
            for (int u = 0; u < 16; ++u) v[u] = itemh[(size_t)d[u] * 32 + lane];
#pragma unroll
            for (int u = 0; u < 16; ++u) {
                const float2 p0 = __bfloat1622float2(*reinterpret_cast<const __nv_bfloat162*>(&v[u].x));
                const float2 p1 = __bfloat1622float2(*reinterpret_cast<const __nv_bfloat162*>(&v[u].y));
                acc.x += c[u] * p0.x; acc.y += c[u] * p0.y;
                acc.z += c[u] * p1.x; acc.w += c[u] * p1.y;
            }
        }
    }

    // warp-reduce score total (fixed order -> deterministic)
#pragma unroll
    for (int o = 16; o; o >>= 1) ssum += __shfl_xor_sync(0xFFFFFFFFu, ssum, o);
    const float inv = (hi > lo) ? 1.f / ssum : 0.f;

    float4 r;
    r.x = 1.f / (1.f + __expf(-acc.x * inv));
    r.y = 1.f / (1.f + __expf(-acc.y * inv));
    r.z = 1.f / (1.f + __expf(-acc.z * inv));
    r.w = 1.f / (1.f + __expf(-acc.w * inv));
    reinterpret_cast<float4*>(out)[(size_t)seg * 32 + lane] = r;
}

// ---------------------------------------------------------------------------
extern "C" void kernel_launch(void* const* d_in, const int* in_sizes, int n_in,
                              void* d_out, int out_size) {
    const float* emb  = (const float*)d_in[0];      // (20001, 128) f32
    const int*   edge = (const int*)d_in[1];        // (640000, 2) int (32/64-bit, sniffed)
    const float* W    = (const float*)d_in[2];      // (128, 128) f32
    const float* b    = (const float*)d_in[3];      // (128,) f32
    const float* Watt = (const float*)d_in[4];      // (256, 1) f32
    const float* batt = (const float*)d_in[5];      // (1,) f32
    float*       out  = (float*)d_out;              // (20001, 128) f32

    k_gemm<<<(M_ITEMS + 63) / 64, 256>>>(emb, W, b, Watt);
    k_edge<<<NE / 256, 256>>>(edge, batt);
    k_agg <<<(M_ITEMS + 1) / 2, 64>>>(out);
}